// round 2
// baseline (speedup 1.0000x reference)
#include <cuda_runtime.h>
#include <math.h>

#define NN 50000
#define EE 800000
#define DD 200
#define RR 230

// ---- scratch (__device__ globals; no allocations allowed) ----
__device__ __align__(128) float g_agg[NN * DD];   // edge aggregation (layer1, then layer2)
__device__ __align__(128) float g_h1[NN * DD];    // layer-1 output
__device__ __align__(128) float g_norm[NN];       // deg -> 1/deg
__device__ __align__(128) float g_WtA[DD * DD];   // W_ih^T  (k-major: [k][j] = Wih[j][k])
__device__ __align__(128) float g_WtB[DD * DD];   // W_hh^T  (k-major)
__device__ __align__(128) float g_Mt[DD * DD];    // lw2 @ Wih^T (k-major)
__device__ __align__(128) float g_bfin[DD];       // bih + bhh + b2 @ Wih^T

// ---------------- degree / norm ----------------
__global__ void deg_kernel(const int* __restrict__ dst) {
    int e = blockIdx.x * blockDim.x + threadIdx.x;
    if (e < EE) atomicAdd(&g_norm[dst[e]], 1.0f);
}

__global__ void norm_kernel() {
    int n = blockIdx.x * blockDim.x + threadIdx.x;
    if (n < NN) {
        float d = g_norm[n];
        g_norm[n] = (d > 0.0f) ? (1.0f / d) : 0.0f;
    }
}

// ---------------- transpose W_ih, W_hh to k-major ----------------
__global__ void transpose_kernel(const float* __restrict__ A, const float* __restrict__ B) {
    int idx = blockIdx.x * blockDim.x + threadIdx.x;
    if (idx < DD * DD) {
        int j = idx / DD, k = idx - j * DD;
        g_WtA[k * DD + j] = A[idx];
        g_WtB[k * DD + j] = B[idx];
    }
}

// ---------------- Mt = lw2 @ Wih^T  (uses g_WtA, coalesced in j) ----------------
__global__ void mt_kernel(const float* __restrict__ lw2) {
    int idx = blockIdx.x * blockDim.x + threadIdx.x;
    if (idx >= DD * DD) return;
    int t = idx / DD, j = idx - t * DD;
    float s = 0.0f;
#pragma unroll 4
    for (int u = 0; u < DD; u++)
        s += __ldg(&lw2[t * DD + u]) * g_WtA[u * DD + j];
    g_Mt[idx] = s;
}

// ---------------- bfin = bih + bhh + b2 @ Wih^T ----------------
__global__ void bias_kernel(const float* __restrict__ b2, const float* __restrict__ Wih,
                            const float* __restrict__ bih, const float* __restrict__ bhh) {
    int j = blockIdx.x * blockDim.x + threadIdx.x;
    if (j >= DD) return;
    float s = bih[j] + bhh[j];
#pragma unroll 4
    for (int t = 0; t < DD; t++)
        s += __ldg(&b2[t]) * __ldg(&Wih[j * DD + t]);
    g_bfin[j] = s;
}

// ---------------- edge message + scatter ----------------
// Thread handles one edge and TWO chunk-pairs (chunks c and c+25), each chunk = 2
// S=2 diagonal blocks -> red.global.add.v4.f32. 25 threads/edge: fewer redundant
// index loads than 50/edge while keeping x/w/RED accesses coalesced.
// w layout: (R, B, S, S) flat = r*400 + b*4 + i*2 + o; chunk cc uses blocks 2cc,2cc+1.
__global__ void edge_kernel(const float* __restrict__ x,
                            const int* __restrict__ src,
                            const int* __restrict__ dst,
                            const int* __restrict__ et,
                            const float* __restrict__ w) {
    int idx = blockIdx.x * blockDim.x + threadIdx.x;   // < EE*25 = 20M
    if (idx >= EE * 25) return;
    int e = idx / 25;
    int c = idx - e * 25;    // chunk ids c and c+25

    int s = __ldg(&src[e]);
    int d = __ldg(&dst[e]);
    int r = __ldg(&et[e]);

    const float4* xp = (const float4*)(x + s * DD);
    float4 xa = xp[c];
    float4 xb = xp[c + 25];
    const float4* wp = (const float4*)(w + r * 400);
    float4 w0 = wp[2 * c];
    float4 w1 = wp[2 * c + 1];
    float4 w2 = wp[2 * c + 50];
    float4 w3 = wp[2 * c + 51];

    float o0 = xa.x * w0.x + xa.y * w0.z;
    float o1 = xa.x * w0.y + xa.y * w0.w;
    float o2 = xa.z * w1.x + xa.w * w1.z;
    float o3 = xa.z * w1.y + xa.w * w1.w;
    float p0 = xb.x * w2.x + xb.y * w2.z;
    float p1 = xb.x * w2.y + xb.y * w2.w;
    float p2 = xb.z * w3.x + xb.w * w3.z;
    float p3 = xb.z * w3.y + xb.w * w3.w;

    float* ap = g_agg + d * DD;
    asm volatile("red.global.add.v4.f32 [%0], {%1, %2, %3, %4};"
                 :: "l"(ap + c * 4), "f"(o0), "f"(o1), "f"(o2), "f"(o3) : "memory");
    asm volatile("red.global.add.v4.f32 [%0], {%1, %2, %3, %4};"
                 :: "l"(ap + (c + 25) * 4), "f"(p0), "f"(p1), "f"(p2), "f"(p3) : "memory");
}

// ---------------- full-width GEMM: out[64 x 200] tiles ----------------
// out[n,j] = act( sum_p sum_k A_p[n,k]*W_p[k,j]  (+ agg[n,j]*norm[n]) + bias[j] )
// A_p optionally row-scaled by norm[n] (SCALE_MASK bit p).
// blockDim (8,32): tx covers col quads {tx+8j : j<6} (cols 0..191) + col 192+tx.
// ty covers rows ty and ty+32. KT=20, 10 k-tiles per pass. All smem accesses
// conflict-free (quad-interleaved W cols; A padded to stride 24).
template <int NPASS, bool TANH, bool HAS_AGG, int SCALE_MASK>
__global__ __launch_bounds__(256, 2) void gemm200(
    const float* __restrict__ A0, const float* __restrict__ W0,
    const float* __restrict__ A1, const float* __restrict__ W1,
    const float* __restrict__ A2, const float* __restrict__ W2,
    const float* __restrict__ bias, float* __restrict__ out) {
    __shared__ float Ws[20 * 200];
    __shared__ float As[64 * 24];   // KT=20 padded to 24

    int tx = threadIdx.x;           // 0..7
    int ty = threadIdx.y;           // 0..31
    int tid = ty * 8 + tx;
    int row0 = blockIdx.x * 64;

    float4 acc0[6], acc1[6];
    float acce0 = 0.0f, acce1 = 0.0f;
#pragma unroll
    for (int j = 0; j < 6; j++) {
        acc0[j] = make_float4(0.f, 0.f, 0.f, 0.f);
        acc1[j] = make_float4(0.f, 0.f, 0.f, 0.f);
    }

#pragma unroll
    for (int p = 0; p < NPASS; p++) {
        const float* A = (p == 0) ? A0 : ((p == 1) ? A1 : A2);
        const float* W = (p == 0) ? W0 : ((p == 1) ? W1 : W2);
        const bool scale = ((SCALE_MASK >> p) & 1) != 0;
        for (int kb = 0; kb < DD; kb += 20) {
            __syncthreads();
            // W tile: 20 x 200 = 1000 float4
            for (int i = tid; i < 1000; i += 256) {
                int k = i / 50, c4 = i - k * 50;
                ((float4*)(Ws + k * 200))[c4] = ((const float4*)(W + (kb + k) * DD))[c4];
            }
            // A tile: 64 rows x 20 cols = 320 float4 (5 per row)
            for (int i = tid; i < 320; i += 256) {
                int rr = i / 5, c4 = i - rr * 5;
                int gr = row0 + rr;
                float4 v = make_float4(0.f, 0.f, 0.f, 0.f);
                if (gr < NN) {
                    v = ((const float4*)(A + gr * DD + kb))[c4];
                    if (scale) {
                        float nv = g_norm[gr];
                        v.x *= nv; v.y *= nv; v.z *= nv; v.w *= nv;
                    }
                }
                ((float4*)(As + rr * 24))[c4] = v;
            }
            __syncthreads();
#pragma unroll
            for (int k = 0; k < 20; k++) {
                float a0 = As[ty * 24 + k];
                float a1 = As[(ty + 32) * 24 + k];
                float we = Ws[k * 200 + 192 + tx];
                acce0 += a0 * we;
                acce1 += a1 * we;
#pragma unroll
                for (int j = 0; j < 6; j++) {
                    float4 wq = *(const float4*)(Ws + k * 200 + (tx + 8 * j) * 4);
                    acc0[j].x += a0 * wq.x; acc0[j].y += a0 * wq.y;
                    acc0[j].z += a0 * wq.z; acc0[j].w += a0 * wq.w;
                    acc1[j].x += a1 * wq.x; acc1[j].y += a1 * wq.y;
                    acc1[j].z += a1 * wq.z; acc1[j].w += a1 * wq.w;
                }
            }
        }
    }

    // epilogue
#pragma unroll
    for (int m = 0; m < 2; m++) {
        int gr = row0 + ty + m * 32;
        if (gr >= NN) continue;
        float nv = HAS_AGG ? g_norm[gr] : 0.0f;
#pragma unroll
        for (int j = 0; j < 6; j++) {
            int col = (tx + 8 * j) * 4;
            float4 v = m ? acc1[j] : acc0[j];
            if (HAS_AGG) {
                float4 a = *(const float4*)(g_agg + gr * DD + col);
                v.x += a.x * nv; v.y += a.y * nv; v.z += a.z * nv; v.w += a.w * nv;
            }
            float4 bb = *(const float4*)(bias + col);
            v.x += bb.x; v.y += bb.y; v.z += bb.z; v.w += bb.w;
            if (TANH) { v.x = tanhf(v.x); v.y = tanhf(v.y); v.z = tanhf(v.z); v.w = tanhf(v.w); }
            *(float4*)(out + gr * DD + col) = v;
        }
        // extra column 192+tx
        int col = 192 + tx;
        float v = m ? acce1 : acce0;
        if (HAS_AGG) v += g_agg[gr * DD + col] * nv;
        v += bias[col];
        if (TANH) v = tanhf(v);
        out[gr * DD + col] = v;
    }
}

// ---------------- launch ----------------
extern "C" void kernel_launch(void* const* d_in, const int* in_sizes, int n_in,
                              void* d_out, int out_size) {
    const float* node_feat = (const float*)d_in[0];
    const float* dyn       = (const float*)d_in[1];   // (N,1,D) contiguous = h0
    const int*   src       = (const int*)d_in[2];
    const int*   dst       = (const int*)d_in[3];
    const int*   et        = (const int*)d_in[4];
    const float* w1        = (const float*)d_in[5];
    const float* lw1       = (const float*)d_in[6];
    const float* b1        = (const float*)d_in[7];
    const float* w2        = (const float*)d_in[8];
    const float* lw2       = (const float*)d_in[9];
    const float* b2        = (const float*)d_in[10];
    const float* Wih       = (const float*)d_in[11];
    const float* Whh       = (const float*)d_in[12];
    const float* bih       = (const float*)d_in[13];
    const float* bhh       = (const float*)d_in[14];
    float* out = (float*)d_out;

    void *agg_p, *norm_p, *h1_p, *wta_p, *wtb_p, *mt_p, *bfin_p;
    cudaGetSymbolAddress(&agg_p, g_agg);
    cudaGetSymbolAddress(&norm_p, g_norm);
    cudaGetSymbolAddress(&h1_p, g_h1);
    cudaGetSymbolAddress(&wta_p, g_WtA);
    cudaGetSymbolAddress(&wtb_p, g_WtB);
    cudaGetSymbolAddress(&mt_p, g_Mt);
    cudaGetSymbolAddress(&bfin_p, g_bfin);

    cudaMemsetAsync(agg_p, 0, sizeof(float) * NN * DD);
    cudaMemsetAsync(norm_p, 0, sizeof(float) * NN);

    deg_kernel<<<(EE + 255) / 256, 256>>>(dst);
    norm_kernel<<<(NN + 255) / 256, 256>>>();
    transpose_kernel<<<(DD * DD + 255) / 256, 256>>>(Wih, Whh);
    mt_kernel<<<(DD * DD + 255) / 256, 256>>>(lw2);
    bias_kernel<<<1, 256>>>(b2, Wih, bih, bhh);

    const int edge_blocks = (EE * 25 + 255) / 256;   // 78125
    dim3 gblk(8, 32);
    int ggrd = (NN + 63) / 64;                       // 782

    // layer 1: scatter, then h1 = tanh(x@lw1 + agg1*norm + b1)
    edge_kernel<<<edge_blocks, 256>>>(node_feat, src, dst, et, w1);
    gemm200<1, true, true, 0><<<ggrd, gblk>>>(
        node_feat, lw1, nullptr, nullptr, nullptr, nullptr, b1, (float*)h1_p);

    // layer 2 scatter
    cudaMemsetAsync(agg_p, 0, sizeof(float) * NN * DD);
    edge_kernel<<<edge_blocks, 256>>>((const float*)h1_p, src, dst, et, w2);

    // fused final: out = tanh( (agg2*norm)@Wih^T + h1@(lw2@Wih^T) + h0@Whh^T + bfin )
    gemm200<3, true, false, 1><<<ggrd, gblk>>>(
        (const float*)agg_p, (const float*)wta_p,
        (const float*)h1_p,  (const float*)mt_p,
        dyn,                 (const float*)wtb_p,
        (const float*)bfin_p, out);
}